// round 11
// baseline (speedup 1.0000x reference)
#include <cuda_runtime.h>
#include <cuda_fp16.h>

// RoiAlign: feature_map (4, 256, 50, 50) f32, boxes (512,4) f32, box_idx (512) i32
// Output: (512, 256, 14, 14) f32
//
// R10: fp16 smem staging + half2 tree compute, 32 regs, occ 85%. Remaining fat
// is staging (16 LDG.32 per 2 cells). R11: align window origin to even x so
// cell-pairs load as 8x LDG.64; right-edge handled by replicate-select.
// Staging LDG count halves; everything else unchanged.

#define CROP    14
#define NPIX    (CROP * CROP)      // 196
#define FM_H    50
#define FM_W    50
#define FM_HW   (FM_H * FM_W)      // 2500
#define NCHAN   256
#define NBOX    512
#define CPB     32                 // channels per block
#define NCG8    (CPB / 8)          // 4 groups of 8 channels
#define WIN     16
#define NCELL   (WIN * WIN)        // 256 cells (fixed layout)
#define THREADS 224                // 7 full warps

struct alignas(16) h2x4 {          // 8 fp16 values = one 16-byte smem cell
    __half2 a, b, c, d;
};

__global__ __launch_bounds__(THREADS, 9) void roi_align_kernel(
    const float* __restrict__ fm,
    const float* __restrict__ boxes,
    const int*   __restrict__ box_idx,
    float*       __restrict__ out)
{
    __shared__ h2x4 s4[NCG8 * NCELL];   // 16 KB

    const int m   = blockIdx.x;               // box
    const int cb  = blockIdx.y * CPB;         // channel base
    const int tid = threadIdx.x;

    // ---- Per-box geometry ----
    const float inv_stride = 1.0f / 16.0f;
    const float inv_span   = 1.0f / (float)(CROP - 1);
    const float bx1 = boxes[m * 4 + 0] * inv_stride;
    const float by1 = boxes[m * 4 + 1] * inv_stride;
    const float bx2 = boxes[m * 4 + 2] * inv_stride;
    const float by2 = boxes[m * 4 + 3] * inv_stride;

    const int ystart = min(max((int)floorf(by1), 0), FM_H - 1);
    const int xstart = min(max((int)floorf(bx1), 0), FM_W - 1);
    const int xs2    = xstart & ~1;           // even-aligned window origin (8B)

    // Trimmed staging extents (+margin for fp rounding at far edge).
    const int yendc = min(max((int)floorf(by2), 0), FM_H - 1);
    const int xendc = min(max((int)floorf(bx2), 0), FM_W - 1);
    const int wyn   = min(yendc - ystart + 3, WIN);
    const int wxn   = min(xendc - xs2 + 3, WIN);
    const int prow  = (wxn + 1) >> 1;         // cell-pairs per row (<=8)

    const int bi = box_idx[m];
    const float* __restrict__ fbase =
        fm + (size_t)bi * NCHAN * FM_HW + (size_t)cb * FM_HW;

    // ---- Stage: cell-pairs via LDG.64; fixed 16-stride fp16 layout ----
    const int tasks = wyn << 3;               // wyn rows x 8 pair-slots
    #pragma unroll
    for (int cg = 0; cg < NCG8; ++cg) {
        const float* __restrict__ fc = fbase + cg * 8 * FM_HW;
        for (int r = tid; r < tasks; r += THREADS) {
            const int ry  = r >> 3;
            const int rxp = r & 7;
            if (rxp < prow) {
                const int gy   = min(ystart + ry, FM_H - 1);
                const int gx   = xs2 + 2 * rxp;
                const int gxp  = min(gx, FM_W - 2);
                const bool repl = gx >= FM_W - 1;   // even cell needs value[49]
                const float2* p = (const float2*)(fc + gy * FM_W + gxp);

                h2x4 e, o;   // even cell (2*rxp), odd cell (2*rxp+1)
                {
                    float2 c0 = __ldg(p);
                    float2 c1 = __ldg(p +     (FM_HW / 2));
                    float2 c2 = __ldg(p + 2 * (FM_HW / 2));
                    float2 c3 = __ldg(p + 3 * (FM_HW / 2));
                    if (repl) { c0.x = c0.y; c1.x = c1.y; c2.x = c2.y; c3.x = c3.y; }
                    e.a = __floats2half2_rn(c0.x, c1.x);
                    o.a = __floats2half2_rn(c0.y, c1.y);
                    e.b = __floats2half2_rn(c2.x, c3.x);
                    o.b = __floats2half2_rn(c2.y, c3.y);
                }
                {
                    float2 c4 = __ldg(p + 4 * (FM_HW / 2));
                    float2 c5 = __ldg(p + 5 * (FM_HW / 2));
                    float2 c6 = __ldg(p + 6 * (FM_HW / 2));
                    float2 c7 = __ldg(p + 7 * (FM_HW / 2));
                    if (repl) { c4.x = c4.y; c5.x = c5.y; c6.x = c6.y; c7.x = c7.y; }
                    e.c = __floats2half2_rn(c4.x, c5.x);
                    o.c = __floats2half2_rn(c4.y, c5.y);
                    e.d = __floats2half2_rn(c6.x, c7.x);
                    o.d = __floats2half2_rn(c6.y, c7.y);
                }
                const int cell = (ry << 4) + 2 * rxp;
                s4[cg * NCELL + cell]     = e;
                s4[cg * NCELL + cell + 1] = o;
            }
        }
    }
    __syncthreads();

    if (tid >= NPIX) return;

    // ---- Per-pixel sampling point ----
    const int iy = tid / CROP;
    const int ix = tid - iy * CROP;

    const float ys = by1 + (float)iy * (by2 - by1) * inv_span;
    const float xs = bx1 + (float)ix * (bx2 - bx1) * inv_span;

    const float y0f = floorf(ys);
    const float x0f = floorf(xs);
    const int y0 = min(max((int)y0f, 0), FM_H - 1);
    const int x0 = min(max((int)x0f, 0), FM_W - 1);
    const int y1 = min(y0 + 1, FM_H - 1);
    const int x1 = min(x0 + 1, FM_W - 1);
    const float wy = ys - y0f;
    const float wx = xs - x0f;
    const float v  = (ys >= 0.0f && ys <= (float)(FM_H - 1) &&
                      xs >= 0.0f && xs <= (float)(FM_W - 1)) ? 1.0f : 0.0f;

    const int l00 = (y0 - ystart) * WIN + (x0 - xs2);
    const int dx  = x1 - x0;            // 0 or 1
    const int dyc = (y1 - y0) * WIN;    // 0 or 16

    // Folded weights (incl. validity), broadcast to half2.
    const __half2 hw00 = __float2half2_rn((1.0f - wx) * (1.0f - wy) * v);
    const __half2 hw01 = __float2half2_rn(wx * (1.0f - wy) * v);
    const __half2 hw10 = __float2half2_rn((1.0f - wx) * wy * v);
    const __half2 hw11 = __float2half2_rn(wx * wy * v);

    float* __restrict__ o =
        out + (size_t)m * NCHAN * NPIX + (size_t)cb * NPIX + tid;

    #pragma unroll
    for (int cg = 0; cg < NCG8; ++cg) {
        const h2x4* sc = s4 + cg * NCELL;
        const h2x4 pa = sc[l00];
        const h2x4 pb = sc[l00 + dx];
        const h2x4 pc = sc[l00 + dyc];
        const h2x4 pd = sc[l00 + dyc + dx];

        float* oc = o + cg * 8 * NPIX;

        #pragma unroll
        for (int j = 0; j < 4; ++j) {
            // Tree form: two independent chains, depth 3.
            __half2 u = __hfma2((&pb.a)[j], hw01, __hmul2((&pa.a)[j], hw00));
            __half2 w = __hfma2((&pd.a)[j], hw11, __hmul2((&pc.a)[j], hw10));
            __half2 r = __hadd2(u, w);
            const float2 rf = __half22float2(r);
            oc[(2 * j)     * NPIX] = rf.x;
            oc[(2 * j + 1) * NPIX] = rf.y;
        }
    }
}

extern "C" void kernel_launch(void* const* d_in, const int* in_sizes, int n_in,
                              void* d_out, int out_size)
{
    const float* fm     = (const float*)d_in[0];
    const float* boxes  = (const float*)d_in[1];
    const int*   boxidx = (const int*)d_in[2];
    float*       out    = (float*)d_out;

    dim3 grid(NBOX, NCHAN / CPB);   // (512, 8) = 4096 blocks
    roi_align_kernel<<<grid, THREADS>>>(fm, boxes, boxidx, out);
}

// round 12
// speedup vs baseline: 1.1141x; 1.1141x over previous
#include <cuda_runtime.h>
#include <cuda_fp16.h>

// RoiAlign: feature_map (4, 256, 50, 50) f32, boxes (512,4) f32, box_idx (512) i32
// Output: (512, 256, 14, 14) f32
//
// R12 = R10 (best: fp16 smem staging, half2 tree compute, 32 regs / occ 85%)
// + software pipeline over channel-groups: stage(cg+1) is issued before
// compute(cg), so staging's L2 latency executes under compute instructions.
// R11's LDG.64 staging reverted (halved active staging threads -> regression).

#define CROP    14
#define NPIX    (CROP * CROP)      // 196
#define FM_H    50
#define FM_W    50
#define FM_HW   (FM_H * FM_W)      // 2500
#define NCHAN   256
#define NBOX    512
#define CPB     32                 // channels per block
#define NCG8    (CPB / 8)          // 4 groups of 8 channels
#define WIN     16
#define NCELL   (WIN * WIN)        // 256 cells (fixed layout)
#define THREADS 224                // 7 full warps

struct alignas(16) h2x4 {          // 8 fp16 values = one 16-byte smem cell
    __half2 a, b, c, d;
};

__global__ __launch_bounds__(THREADS, 9) void roi_align_kernel(
    const float* __restrict__ fm,
    const float* __restrict__ boxes,
    const int*   __restrict__ box_idx,
    float*       __restrict__ out)
{
    __shared__ h2x4 s4[NCG8 * NCELL];   // 16 KB

    const int m   = blockIdx.x;               // box
    const int cb  = blockIdx.y * CPB;         // channel base
    const int tid = threadIdx.x;

    // ---- Per-box geometry ----
    const float inv_stride = 1.0f / 16.0f;
    const float inv_span   = 1.0f / (float)(CROP - 1);
    const float bx1 = boxes[m * 4 + 0] * inv_stride;
    const float by1 = boxes[m * 4 + 1] * inv_stride;
    const float bx2 = boxes[m * 4 + 2] * inv_stride;
    const float by2 = boxes[m * 4 + 3] * inv_stride;

    const int ystart = min(max((int)floorf(by1), 0), FM_H - 1);
    const int xstart = min(max((int)floorf(bx1), 0), FM_W - 1);

    // Trimmed staging extents (+margin for fp rounding at far edge).
    const int yendc = min(max((int)floorf(by2), 0), FM_H - 1);
    const int xendc = min(max((int)floorf(bx2), 0), FM_W - 1);
    const int wyn = min(yendc - ystart + 3, WIN);
    const int wxn = min(xendc - xstart + 3, WIN);
    const int cells = wyn << 4;               // wyn rows x 16 (fixed stride)

    const int bi = box_idx[m];
    const float* __restrict__ fbase =
        fm + (size_t)bi * NCHAN * FM_HW + (size_t)cb * FM_HW;

    // ---- Per-pixel sampling state (computed up front; valid for tid<196) ----
    const int iy = tid / CROP;
    const int ix = tid - iy * CROP;

    const float ys = by1 + (float)iy * (by2 - by1) * inv_span;
    const float xs = bx1 + (float)ix * (bx2 - bx1) * inv_span;

    const float y0f = floorf(ys);
    const float x0f = floorf(xs);
    const int y0 = min(max((int)y0f, 0), FM_H - 1);
    const int x0 = min(max((int)x0f, 0), FM_W - 1);
    const int y1 = min(y0 + 1, FM_H - 1);
    const int x1 = min(x0 + 1, FM_W - 1);
    const float wy = ys - y0f;
    const float wx = xs - x0f;
    const float v  = (ys >= 0.0f && ys <= (float)(FM_H - 1) &&
                      xs >= 0.0f && xs <= (float)(FM_W - 1)) ? 1.0f : 0.0f;

    const int l00 = (y0 - ystart) * WIN + (x0 - xstart);
    const int dx  = x1 - x0;            // 0 or 1
    const int dyc = (y1 - y0) * WIN;    // 0 or 16

    const __half2 hw00 = __float2half2_rn((1.0f - wx) * (1.0f - wy) * v);
    const __half2 hw01 = __float2half2_rn(wx * (1.0f - wy) * v);
    const __half2 hw10 = __float2half2_rn((1.0f - wx) * wy * v);
    const __half2 hw11 = __float2half2_rn(wx * wy * v);

    float* __restrict__ o =
        out + (size_t)m * NCHAN * NPIX + (size_t)cb * NPIX + tid;

    // ---- Staging helper (R10 form: 16 tasks/row, 8x LDG.32 per task) ----
    auto stage_cg = [&](int cg) {
        const float* __restrict__ fc = fbase + cg * 8 * FM_HW;
        for (int r = tid; r < cells; r += THREADS) {
            const int ry = r >> 4;
            const int rx = r & 15;
            if (rx < wxn) {
                const int gy = min(ystart + ry, FM_H - 1);
                const int gx = min(xstart + rx, FM_W - 1);
                const float* p = fc + gy * FM_W + gx;
                h2x4 packed;
                packed.a = __float22half2_rn(make_float2(__ldg(p),             __ldg(p + FM_HW)));
                packed.b = __float22half2_rn(make_float2(__ldg(p + 2 * FM_HW), __ldg(p + 3 * FM_HW)));
                packed.c = __float22half2_rn(make_float2(__ldg(p + 4 * FM_HW), __ldg(p + 5 * FM_HW)));
                packed.d = __float22half2_rn(make_float2(__ldg(p + 6 * FM_HW), __ldg(p + 7 * FM_HW)));
                s4[cg * NCELL + r] = packed;
            }
        }
    };

    // ---- Pipelined: stage(cg+1) issued before compute(cg) ----
    stage_cg(0);
    __syncthreads();

    #pragma unroll
    for (int cg = 0; cg < NCG8; ++cg) {
        if (cg + 1 < NCG8) stage_cg(cg + 1);

        if (tid < NPIX) {
            const h2x4* sc = s4 + cg * NCELL;
            const h2x4 pa = sc[l00];
            const h2x4 pb = sc[l00 + dx];
            const h2x4 pc = sc[l00 + dyc];
            const h2x4 pd = sc[l00 + dyc + dx];

            float* oc = o + cg * 8 * NPIX;

            #pragma unroll
            for (int j = 0; j < 4; ++j) {
                __half2 u = __hfma2((&pb.a)[j], hw01, __hmul2((&pa.a)[j], hw00));
                __half2 w = __hfma2((&pd.a)[j], hw11, __hmul2((&pc.a)[j], hw10));
                __half2 r = __hadd2(u, w);
                const float2 rf = __half22float2(r);
                oc[(2 * j)     * NPIX] = rf.x;
                oc[(2 * j + 1) * NPIX] = rf.y;
            }
        }
        if (cg + 1 < NCG8) __syncthreads();
    }
}

extern "C" void kernel_launch(void* const* d_in, const int* in_sizes, int n_in,
                              void* d_out, int out_size)
{
    const float* fm     = (const float*)d_in[0];
    const float* boxes  = (const float*)d_in[1];
    const int*   boxidx = (const int*)d_in[2];
    float*       out    = (float*)d_out;

    dim3 grid(NBOX, NCHAN / CPB);   // (512, 8) = 4096 blocks
    roi_align_kernel<<<grid, THREADS>>>(fm, boxes, boxidx, out);
}